// round 6
// baseline (speedup 1.0000x reference)
#include <cuda_runtime.h>

// DiffKS split pipeline v2:
//   Kernel A (FIR, sample-parallel): x[t] = y[t] + sum_k Ae[t,k]*y[t-1-k],
//     written in chunk-phase PERMUTED layout xp[i*NTOT + chunk] via in-block
//     smem transpose, so kernel B's x loads are fully coalesced. Warm windows
//     (last 32 samples of each chunk) are duplicated into the next chunk's
//     i=0..7 slots.
//   Kernel B (IIR, chunk-per-thread + warmup): out[t] = x[t] - a1*out[t-1] - a2*out[t-2]
//     CHUNK=128, WARM=32 (contraction 0.64^32 ~ 6e-7 << 1e-3); chunk 0 exact
//     via state reset at t==0 (warm outputs never stored).

#define BATCH 48
#define TLEN  88200
#define T4    22050                  // float4 per row of y / x
#define NCH   690                    // ceil(88200/128) chunks per row
#define NTOT  (BATCH * NCH)          // 33120
#define ITERS 40                     // (128+32)/4 f4-iterations per chunk

#define AE_F4_ROW 132300             // TLEN*6/4
#define Y_F4_ROW  22050
#define AL_F4_ROW 44100              // TLEN*2/4

__device__ float4 g_xp[ITERS * NTOT];   // permuted x scratch (21.2 MB)

// ---------------- Kernel A: FIR + permuted store ----------------
#define TPB_A 256
#define BPR_A 87                      // blocks per row: 87*8 chunks >= 690

__global__ void __launch_bounds__(TPB_A)
fir_kernel(const float* __restrict__ y, const float* __restrict__ Ae)
{
    __shared__ float4 sAe[TPB_A * 7];   // pitch 7 -> conflict-free LDS.128
    __shared__ float4 sY[260];          // 2 halo + 256 tile + pad
    __shared__ float4 sx[8 * 33];       // transpose buffer, pitch 33

    const int tid = threadIdx.x;
    const int b   = blockIdx.x / BPR_A;
    const int blk = blockIdx.x % BPR_A;
    const int B0  = blk * 256;          // f4 base within row
    const int c0  = blk * 8;            // first chunk of block

    const float4* yg  = reinterpret_cast<const float4*>(y)  + (size_t)b * Y_F4_ROW;
    const float4* aeg = reinterpret_cast<const float4*>(Ae) + (size_t)b * AE_F4_ROW;

    // stage Ae tile: 1536 f4 flat coalesced -> pitch-7 scatter
    {
        const int base6 = B0 * 6;
        #pragma unroll
        for (int j = 0; j < 6; j++) {
            int f = tid + TPB_A * j;                 // 0..1535
            int gi = min(base6 + f, AE_F4_ROW - 1);
            int w = f / 6, k = f - 6 * w;
            sAe[w * 7 + k] = aeg[gi];
        }
    }
    // stage y tile + 2-f4 front halo
    {
        int gi = B0 - 2 + tid;
        sY[tid] = (gi < 0) ? make_float4(0.f, 0.f, 0.f, 0.f)
                           : yg[min(gi, Y_F4_ROW - 1)];
        if (tid < 4) {
            int l = TPB_A + tid;
            int gi2 = B0 - 2 + l;
            sY[l] = (gi2 < 0) ? make_float4(0.f, 0.f, 0.f, 0.f)
                              : yg[min(gi2, Y_F4_ROW - 1)];
        }
    }
    __syncthreads();

    // compute 4 samples (t4 = B0 + tid)
    float4 y4  = sY[2 + tid];
    float4 ym1 = sY[1 + tid];
    float4 ym2 = sY[tid];
    float h0 = ym1.w, h1 = ym1.z, h2 = ym1.y, h3 = ym1.x;
    float h4 = ym2.w, h5 = ym2.z;

    float4 e0 = sAe[tid * 7 + 0];
    float4 e1 = sAe[tid * 7 + 1];
    float4 e2 = sAe[tid * 7 + 2];
    float4 e3 = sAe[tid * 7 + 3];
    float4 e4 = sAe[tid * 7 + 4];
    float4 e5 = sAe[tid * 7 + 5];

    float4 x4;
    x4.x = y4.x + e0.x*h0 + e0.y*h1 + e0.z*h2 + e0.w*h3 + e1.x*h4 + e1.y*h5;
    h5 = h4; h4 = h3; h3 = h2; h2 = h1; h1 = h0; h0 = y4.x;
    x4.y = y4.y + e1.z*h0 + e1.w*h1 + e2.x*h2 + e2.y*h3 + e2.z*h4 + e2.w*h5;
    h5 = h4; h4 = h3; h3 = h2; h2 = h1; h1 = h0; h0 = y4.y;
    x4.z = y4.z + e3.x*h0 + e3.y*h1 + e3.z*h2 + e3.w*h3 + e4.x*h4 + e4.y*h5;
    h5 = h4; h4 = h3; h3 = h2; h2 = h1; h1 = h0; h0 = y4.z;
    x4.w = y4.w + e4.z*h0 + e4.w*h1 + e5.x*h2 + e5.y*h3 + e5.z*h4 + e5.w*h5;

    // transpose through smem: warp w (=chunk local cl) lane j -> sx[cl*33+j]
    {
        int cl = tid >> 5, j = tid & 31;
        sx[cl * 33 + j] = x4;
    }
    __syncthreads();

    // home stores: slot (chunk cc, i=8+j), coalesced runs of 8 chunks
    {
        int j2  = tid >> 3;          // 0..31
        int cl2 = tid & 7;           // 0..7
        int t4s = B0 + cl2 * 32 + j2;
        int cc  = c0 + cl2;
        if (t4s < T4 && cc < NCH)
            g_xp[(size_t)(8 + j2) * NTOT + b * NCH + cc] = sx[cl2 * 33 + j2];
    }
    // warm duplicate stores: last 8 f4 of chunk -> next chunk's slots i=0..7
    if (tid < 64) {
        int jw  = tid >> 3;          // 0..7
        int cl2 = tid & 7;           // 0..7
        int t4s = B0 + cl2 * 32 + 24 + jw;
        int cc  = c0 + cl2 + 1;
        if (t4s < T4 && cc < NCH)
            g_xp[(size_t)jw * NTOT + b * NCH + cc] = sx[cl2 * 33 + 24 + jw];
    }
}

// ---------------- Kernel B: IIR (chunk-per-thread, coalesced x) ----------------
#define TPB_B 128

__global__ void __launch_bounds__(TPB_B)
iir_kernel(const float* __restrict__ Al, float* __restrict__ out)
{
    int g = blockIdx.x * TPB_B + threadIdx.x;
    if (g >= NTOT) return;

    int b = g / NCH;
    int c = g - b * NCH;
    int start = c * 128;
    int tend  = min(start + 128, TLEN);

    const float4* al4 = reinterpret_cast<const float4*>(Al) + (size_t)b * AL_F4_ROW;
    float*        ob  = out + (size_t)b * TLEN;

    float s1 = 0.f, s2 = 0.f;

    // prologue: i = 0
    float4 x4 = g_xp[g];
    {
        int t0 = start - 32;
        int af = min(max(t0, 0) >> 1, AL_F4_ROW - 2);
        // fallthrough into loop-carried regs
        s1 = 0.f; s2 = 0.f;
        float4 l0 = al4[af], l1 = al4[af + 1];

        for (int i = 0; i < ITERS; i++) {
            int t = start - 32 + 4 * i;

            // prefetch i+1 (clamped on last iter -> cache hit)
            int in  = min(i + 1, ITERS - 1);
            float4 nx4 = g_xp[(size_t)in * NTOT + g];
            int tn  = start - 32 + 4 * in;
            int afn = min(max(tn, 0) >> 1, AL_F4_ROW - 2);
            float4 nl0 = al4[afn], nl1 = al4[afn + 1];

            if (t == 0) { s1 = 0.f; s2 = 0.f; }   // exact state at sequence start

            float4 o4; float yo;
            yo = x4.x - l0.x*s1 - l0.y*s2;  s2 = s1; s1 = yo; o4.x = yo;
            yo = x4.y - l0.z*s1 - l0.w*s2;  s2 = s1; s1 = yo; o4.y = yo;
            yo = x4.z - l1.x*s1 - l1.y*s2;  s2 = s1; s1 = yo; o4.z = yo;
            yo = x4.w - l1.z*s1 - l1.w*s2;  s2 = s1; s1 = yo; o4.w = yo;

            if (t >= start && t < tend)
                *reinterpret_cast<float4*>(ob + t) = o4;

            x4 = nx4; l0 = nl0; l1 = nl1;
        }
    }
}

extern "C" void kernel_launch(void* const* d_in, const int* in_sizes, int n_in,
                              void* d_out, int out_size)
{
    const float* y  = (const float*)d_in[0];
    const float* Ae = (const float*)d_in[1];
    const float* Al = (const float*)d_in[2];
    float* out = (float*)d_out;

    fir_kernel<<<BATCH * BPR_A, TPB_A>>>(y, Ae);
    iir_kernel<<<(NTOT + TPB_B - 1) / TPB_B, TPB_B>>>(Al, out);
}

// round 7
// speedup vs baseline: 1.0691x; 1.0691x over previous
#include <cuda_runtime.h>

// DiffKS fully fused: FIR (order 6) + order-2 IIR via warp-parallel affine scan.
//   x[t]  = y[t] + sum_{k=1..6} Ae[t,k-1]*y[t-k]
//   out[t]= x[t] - a1[t]*out[t-1] - a2[t]*out[t-2]
// State s=(out[t-1],out[t-2]) evolves by s' = A_t s + b_t; composition of
// affine maps is associative -> Hillis-Steele scan across 32 lanes (4 samples
// each). Warm halo of 32 samples per 128-sample warp chunk reconstructs the
// incoming state from zero init (|a|<=0.25 -> contraction ~0.64/step -> ~6e-7).
// Chunk at t=0 is exact (state forced to zero).
// All global accesses coalesced; smem staging with odd pitches (7,3) for
// conflict-free LDS.128.

#define BATCH 48
#define TLEN  88200
#define T4    22050
#define Y_F4_ROW  22050
#define AE_F4_ROW 132300
#define AL_F4_ROW 44100

#define TPB   128
#define BPR   173                 // blocks per row: 173*128 f4 >= 22050
#define NGRP  136                 // local f4 groups: 8 warm + 128 main
#define FULLM 0xffffffffu

// apply one IIR step (a1,a2,x) on top of affine map (m,v): s' = A s + b
#define MAP_STEP(a1, a2, x)                                   \
    do {                                                      \
        float t00 = -(a1*m00 + a2*m10);                       \
        float t01 = -(a1*m01 + a2*m11);                       \
        float tv0 = x - a1*v0 - a2*v1;                        \
        m10 = m00; m11 = m01; v1 = v0;                        \
        m00 = t00; m01 = t01; v0 = tv0;                       \
    } while (0)

__global__ void __launch_bounds__(TPB)
diffks_fused(const float* __restrict__ y, const float* __restrict__ Ae,
             const float* __restrict__ Al, float* __restrict__ out)
{
    __shared__ float4 sY[NGRP + 3];      // groups G0-2 .. G0+135 (139 slots)
    __shared__ float4 sAe[NGRP * 7];     // pitch 7, conflict-free
    __shared__ float4 sAl[NGRP * 3];     // pitch 3, conflict-free

    const int tid  = threadIdx.x;
    const int lane = tid & 31;
    const int wrp  = tid >> 5;
    const int b    = blockIdx.x / BPR;
    const int blk  = blockIdx.x % BPR;
    const int G0   = blk * 128 - 8;      // global f4 index of local group 0

    const float4* yg  = (const float4*)y  + (size_t)b * Y_F4_ROW;
    const float4* aeg = (const float4*)Ae + (size_t)b * AE_F4_ROW;
    const float4* alg = (const float4*)Al + (size_t)b * AL_F4_ROW;

    // ---------------- stage (all coalesced) ----------------
    {
        int gi = G0 - 2 + tid;
        sY[tid] = (gi < 0) ? make_float4(0.f,0.f,0.f,0.f)
                           : yg[min(gi, Y_F4_ROW - 1)];
        if (tid < 10) {
            int l = TPB + tid, gi2 = G0 - 2 + l;
            sY[l] = (gi2 < 0) ? make_float4(0.f,0.f,0.f,0.f)
                              : yg[min(gi2, Y_F4_ROW - 1)];
        }
    }
    #pragma unroll
    for (int j = 0; j < 7; j++) {        // Ae: 816 f4
        int f = tid + TPB * j;
        if (f < NGRP * 6) {
            int gi = min(max(G0 * 6 + f, 0), AE_F4_ROW - 1);
            int g = f / 6, k = f - 6 * g;
            sAe[g * 7 + k] = aeg[gi];
        }
    }
    #pragma unroll
    for (int j = 0; j < 3; j++) {        // Al: 272 f4
        int f = tid + TPB * j;
        if (f < NGRP * 2) {
            int gi = min(max(G0 * 2 + f, 0), AL_F4_ROW - 1);
            int g = f >> 1, k = f & 1;
            sAl[g * 3 + k] = alg[gi];
        }
    }
    __syncthreads();

    // FIR + affine-map builder for local group g
    auto firmap = [&](int g, float4& x4, float4& l0, float4& l1,
                      float& m00, float& m01, float& m10, float& m11,
                      float& v0, float& v1) {
        float4 y4  = sY[g + 2];
        float4 ym1 = sY[g + 1];
        float4 ym2 = sY[g];
        float h0 = ym1.w, h1 = ym1.z, h2 = ym1.y, h3 = ym1.x;
        float h4 = ym2.w, h5 = ym2.z;
        float4 e0 = sAe[g*7+0], e1 = sAe[g*7+1], e2 = sAe[g*7+2];
        float4 e3 = sAe[g*7+3], e4 = sAe[g*7+4], e5 = sAe[g*7+5];
        l0 = sAl[g*3+0]; l1 = sAl[g*3+1];

        x4.x = y4.x + e0.x*h0 + e0.y*h1 + e0.z*h2 + e0.w*h3 + e1.x*h4 + e1.y*h5;
        h5=h4; h4=h3; h3=h2; h2=h1; h1=h0; h0=y4.x;
        x4.y = y4.y + e1.z*h0 + e1.w*h1 + e2.x*h2 + e2.y*h3 + e2.z*h4 + e2.w*h5;
        h5=h4; h4=h3; h3=h2; h2=h1; h1=h0; h0=y4.y;
        x4.z = y4.z + e3.x*h0 + e3.y*h1 + e3.z*h2 + e3.w*h3 + e4.x*h4 + e4.y*h5;
        h5=h4; h4=h3; h3=h2; h2=h1; h1=h0; h0=y4.z;
        x4.w = y4.w + e4.z*h0 + e4.w*h1 + e5.x*h2 + e5.y*h3 + e5.z*h4 + e5.w*h5;

        // 4-step affine map: s_out = M s_in + v
        m00 = -l0.x; m01 = -l0.y; m10 = 1.f; m11 = 0.f; v0 = x4.x; v1 = 0.f;
        MAP_STEP(l0.z, l0.w, x4.y);
        MAP_STEP(l1.x, l1.y, x4.z);
        MAP_STEP(l1.z, l1.w, x4.w);
    };

    // ---------------- warm sub-scan (lanes 0-7) ----------------
    float wm00 = 1.f, wm01 = 0.f, wm10 = 0.f, wm11 = 1.f, wv0 = 0.f, wv1 = 0.f;
    if (lane < 8) {
        float4 wx4, wl0, wl1;
        firmap(32 * wrp + lane, wx4, wl0, wl1, wm00, wm01, wm10, wm11, wv0, wv1);
    }
    #pragma unroll
    for (int d = 1; d <= 4; d <<= 1) {
        float om00 = __shfl_up_sync(FULLM, wm00, d);
        float om01 = __shfl_up_sync(FULLM, wm01, d);
        float om10 = __shfl_up_sync(FULLM, wm10, d);
        float om11 = __shfl_up_sync(FULLM, wm11, d);
        float ov0  = __shfl_up_sync(FULLM, wv0,  d);
        float ov1  = __shfl_up_sync(FULLM, wv1,  d);
        if (lane >= d) {
            float n00 = wm00*om00 + wm01*om10;
            float n01 = wm00*om01 + wm01*om11;
            float n10 = wm10*om00 + wm11*om10;
            float n11 = wm10*om01 + wm11*om11;
            float nv0 = wm00*ov0 + wm01*ov1 + wv0;
            float nv1 = wm10*ov0 + wm11*ov1 + wv1;
            wm00=n00; wm01=n01; wm10=n10; wm11=n11; wv0=nv0; wv1=nv1;
        }
    }
    float ws0 = __shfl_sync(FULLM, wv0, 7);   // warm state = full warm map @ zero init
    float ws1 = __shfl_sync(FULLM, wv1, 7);
    if (blk == 0 && wrp == 0) { ws0 = 0.f; ws1 = 0.f; }   // exact at sequence start

    // ---------------- main maps + 32-lane scan ----------------
    float4 x4, l0, l1;
    float m00, m01, m10, m11, v0, v1;
    firmap(8 + 32 * wrp + lane, x4, l0, l1, m00, m01, m10, m11, v0, v1);

    float im00 = m00, im01 = m01, im10 = m10, im11 = m11, iv0 = v0, iv1 = v1;
    #pragma unroll
    for (int d = 1; d <= 16; d <<= 1) {
        float om00 = __shfl_up_sync(FULLM, im00, d);
        float om01 = __shfl_up_sync(FULLM, im01, d);
        float om10 = __shfl_up_sync(FULLM, im10, d);
        float om11 = __shfl_up_sync(FULLM, im11, d);
        float ov0  = __shfl_up_sync(FULLM, iv0,  d);
        float ov1  = __shfl_up_sync(FULLM, iv1,  d);
        if (lane >= d) {
            float n00 = im00*om00 + im01*om10;
            float n01 = im00*om01 + im01*om11;
            float n10 = im10*om00 + im11*om10;
            float n11 = im10*om01 + im11*om11;
            float nv0 = im00*ov0 + im01*ov1 + iv0;
            float nv1 = im10*ov0 + im11*ov1 + iv1;
            im00=n00; im01=n01; im10=n10; im11=n11; iv0=nv0; iv1=nv1;
        }
    }
    // exclusive prefix
    float em00 = __shfl_up_sync(FULLM, im00, 1);
    float em01 = __shfl_up_sync(FULLM, im01, 1);
    float em10 = __shfl_up_sync(FULLM, im10, 1);
    float em11 = __shfl_up_sync(FULLM, im11, 1);
    float ev0  = __shfl_up_sync(FULLM, iv0,  1);
    float ev1  = __shfl_up_sync(FULLM, iv1,  1);
    if (lane == 0) { em00 = 1.f; em01 = 0.f; em10 = 0.f; em11 = 1.f; ev0 = 0.f; ev1 = 0.f; }

    // incoming state for this lane
    float s1 = em00 * ws0 + em01 * ws1 + ev0;
    float s2 = em10 * ws0 + em11 * ws1 + ev1;

    // serial replay of 4 samples
    float4 o;
    o.x = x4.x - l0.x*s1 - l0.y*s2;  s2 = s1; s1 = o.x;
    o.y = x4.y - l0.z*s1 - l0.w*s2;  s2 = s1; s1 = o.y;
    o.z = x4.z - l1.x*s1 - l1.y*s2;  s2 = s1; s1 = o.z;
    o.w = x4.w - l1.z*s1 - l1.w*s2;

    int Gm = blk * 128 + tid;            // = G0 + 8 + tid
    if (Gm < T4) {
        reinterpret_cast<float4*>(out + (size_t)b * TLEN)[Gm] = o;
    }
}

extern "C" void kernel_launch(void* const* d_in, const int* in_sizes, int n_in,
                              void* d_out, int out_size)
{
    const float* y  = (const float*)d_in[0];
    const float* Ae = (const float*)d_in[1];
    const float* Al = (const float*)d_in[2];
    float* out = (float*)d_out;

    diffks_fused<<<BATCH * BPR, TPB>>>(y, Ae, Al, out);
}

// round 8
// speedup vs baseline: 1.3775x; 1.2884x over previous
#include <cuda_runtime.h>

// DiffKS fused: FIR (order 6) + order-2 IIR via warp-parallel affine scan,
// 8 samples per thread (one warp = 256 samples + 32-sample warm halo).
//   x[t]  = y[t] + sum_{k=1..6} Ae[t,k-1]*y[t-k]
//   out[t]= x[t] - a1[t]*out[t-1] - a2[t]*out[t-2]
// State s=(out[t-1],out[t-2]): s' = A_t s + b_t; affine composition scanned
// across lanes (Hillis-Steele, 5 steps). Warm halo rebuilds warp-entry state
// from zero init (|a|<=0.25 -> contraction ~0.64/step -> ~6e-7 rel).
// Warp 0 of block 0 of each row forces exact zero state (t=0 chunk exact).
// Smem layouts pair-granular with odd pitches (13 / 5) -> conflict-free LDS.128
// under the stride-2-group access of 8-sample threads.

#define BATCH 48
#define TLEN  88200
#define T4    22050
#define Y_F4_ROW  22050
#define AE_F4_ROW 132300
#define AL_F4_ROW 44100

#define TPB   128
#define BPR   87                  // blocks per row: 87*256 f4 >= 22050
#define NGRP  264                 // 8 warm + 256 main f4-groups per block
#define NPAIR 132
#define FULLM 0xffffffffu

__device__ __forceinline__ void map_step(float a1, float a2, float x,
                                         float& m00, float& m01, float& m10,
                                         float& m11, float& v0, float& v1)
{
    float t00 = -(a1*m00 + a2*m10);
    float t01 = -(a1*m01 + a2*m11);
    float tv0 = x - a1*v0 - a2*v1;
    m10 = m00; m11 = m01; v1 = v0;
    m00 = t00; m01 = t01; v0 = tv0;
}

__global__ void __launch_bounds__(TPB)
diffks_fused(const float* __restrict__ y, const float* __restrict__ Ae,
             const float* __restrict__ Al, float* __restrict__ out)
{
    __shared__ float4 sY[268];            // sY[l] = y f4 (G0-2+l)
    __shared__ float4 sAe[NPAIR * 13];    // pair p: 12 f4 at pitch 13
    __shared__ float4 sAl[NPAIR * 5];     // pair p: 4 f4 at pitch 5

    const int tid  = threadIdx.x;
    const int lane = tid & 31;
    const int wrp  = tid >> 5;
    const int b    = blockIdx.x / BPR;
    const int blk  = blockIdx.x % BPR;
    const int G0   = blk * 256 - 8;       // global f4 index of local group 0

    const float4* yg  = (const float4*)y  + (size_t)b * Y_F4_ROW;
    const float4* aeg = (const float4*)Ae + (size_t)b * AE_F4_ROW;
    const float4* alg = (const float4*)Al + (size_t)b * AL_F4_ROW;

    // ---------------- stage (all coalesced LDG.128) ----------------
    #pragma unroll
    for (int j = 0; j < 3; j++) {                    // y: 266 f4
        int f = tid + TPB * j;
        if (f < 266) {
            int gi = G0 - 2 + f;
            sY[f] = (gi < 0) ? make_float4(0.f,0.f,0.f,0.f)
                             : yg[min(gi, Y_F4_ROW - 1)];
        }
    }
    #pragma unroll
    for (int j = 0; j < 13; j++) {                   // Ae: 1584 f4
        int f = tid + TPB * j;
        if (f < NGRP * 6) {
            int gi = min(max(G0 * 6 + f, 0), AE_F4_ROW - 1);
            int p = f / 12, k = f - 12 * p;
            sAe[p * 13 + k] = aeg[gi];
        }
    }
    #pragma unroll
    for (int j = 0; j < 5; j++) {                    // Al: 528 f4
        int f = tid + TPB * j;
        if (f < NGRP * 2) {
            int gi = min(max(G0 * 2 + f, 0), AL_F4_ROW - 1);
            int p = f >> 2, k = f & 3;
            sAl[p * 5 + k] = alg[gi];
        }
    }
    __syncthreads();

    // FIR for local group g (4 samples): returns x4 and the group's Al f4s
    auto fir4 = [&](int g, float4& x4, float4& l0, float4& l1) {
        const float4* aeP = &sAe[(g >> 1) * 13 + (g & 1) * 6];
        const float4* alP = &sAl[(g >> 1) * 5  + (g & 1) * 2];
        float4 y4  = sY[g + 2];
        float4 ym1 = sY[g + 1];
        float4 ym2 = sY[g];
        float h0 = ym1.w, h1 = ym1.z, h2 = ym1.y, h3 = ym1.x;
        float h4 = ym2.w, h5 = ym2.z;
        float4 e0 = aeP[0], e1 = aeP[1], e2 = aeP[2];
        float4 e3 = aeP[3], e4 = aeP[4], e5 = aeP[5];
        l0 = alP[0]; l1 = alP[1];

        x4.x = y4.x + e0.x*h0 + e0.y*h1 + e0.z*h2 + e0.w*h3 + e1.x*h4 + e1.y*h5;
        h5=h4; h4=h3; h3=h2; h2=h1; h1=h0; h0=y4.x;
        x4.y = y4.y + e1.z*h0 + e1.w*h1 + e2.x*h2 + e2.y*h3 + e2.z*h4 + e2.w*h5;
        h5=h4; h4=h3; h3=h2; h2=h1; h1=h0; h0=y4.y;
        x4.z = y4.z + e3.x*h0 + e3.y*h1 + e3.z*h2 + e3.w*h3 + e4.x*h4 + e4.y*h5;
        h5=h4; h4=h3; h3=h2; h2=h1; h1=h0; h0=y4.z;
        x4.w = y4.w + e4.z*h0 + e4.w*h1 + e5.x*h2 + e5.y*h3 + e5.z*h4 + e5.w*h5;
    };

    // ---------------- warm sub-scan (lanes 0-7, one group each) ----------------
    float wm00 = 1.f, wm01 = 0.f, wm10 = 0.f, wm11 = 1.f, wv0 = 0.f, wv1 = 0.f;
    if (lane < 8) {
        float4 wx4, wl0, wl1;
        fir4(64 * wrp + lane, wx4, wl0, wl1);
        wm00 = -wl0.x; wm01 = -wl0.y; wm10 = 1.f; wm11 = 0.f; wv0 = wx4.x; wv1 = 0.f;
        map_step(wl0.z, wl0.w, wx4.y, wm00, wm01, wm10, wm11, wv0, wv1);
        map_step(wl1.x, wl1.y, wx4.z, wm00, wm01, wm10, wm11, wv0, wv1);
        map_step(wl1.z, wl1.w, wx4.w, wm00, wm01, wm10, wm11, wv0, wv1);
    }
    #pragma unroll
    for (int d = 1; d <= 4; d <<= 1) {
        float om00 = __shfl_up_sync(FULLM, wm00, d);
        float om01 = __shfl_up_sync(FULLM, wm01, d);
        float om10 = __shfl_up_sync(FULLM, wm10, d);
        float om11 = __shfl_up_sync(FULLM, wm11, d);
        float ov0  = __shfl_up_sync(FULLM, wv0,  d);
        float ov1  = __shfl_up_sync(FULLM, wv1,  d);
        if (lane >= d) {
            float n00 = wm00*om00 + wm01*om10;
            float n01 = wm00*om01 + wm01*om11;
            float n10 = wm10*om00 + wm11*om10;
            float n11 = wm10*om01 + wm11*om11;
            float nv0 = wm00*ov0 + wm01*ov1 + wv0;
            float nv1 = wm10*ov0 + wm11*ov1 + wv1;
            wm00=n00; wm01=n01; wm10=n10; wm11=n11; wv0=nv0; wv1=nv1;
        }
    }
    float ws0 = __shfl_sync(FULLM, wv0, 7);
    float ws1 = __shfl_sync(FULLM, wv1, 7);
    if (blk == 0 && wrp == 0) { ws0 = 0.f; ws1 = 0.f; }   // exact at t = 0

    // ---------------- main: 2 groups / thread, 8-step map ----------------
    const int g0 = 8 + 64 * wrp + 2 * lane;
    float4 xa, l0a, l1a, xb, l0b, l1b;
    fir4(g0,     xa, l0a, l1a);
    fir4(g0 + 1, xb, l0b, l1b);

    float m00 = -l0a.x, m01 = -l0a.y, m10 = 1.f, m11 = 0.f, v0 = xa.x, v1 = 0.f;
    map_step(l0a.z, l0a.w, xa.y, m00, m01, m10, m11, v0, v1);
    map_step(l1a.x, l1a.y, xa.z, m00, m01, m10, m11, v0, v1);
    map_step(l1a.z, l1a.w, xa.w, m00, m01, m10, m11, v0, v1);
    map_step(l0b.x, l0b.y, xb.x, m00, m01, m10, m11, v0, v1);
    map_step(l0b.z, l0b.w, xb.y, m00, m01, m10, m11, v0, v1);
    map_step(l1b.x, l1b.y, xb.z, m00, m01, m10, m11, v0, v1);
    map_step(l1b.z, l1b.w, xb.w, m00, m01, m10, m11, v0, v1);

    // 32-lane inclusive scan of 8-sample maps
    float im00 = m00, im01 = m01, im10 = m10, im11 = m11, iv0 = v0, iv1 = v1;
    #pragma unroll
    for (int d = 1; d <= 16; d <<= 1) {
        float om00 = __shfl_up_sync(FULLM, im00, d);
        float om01 = __shfl_up_sync(FULLM, im01, d);
        float om10 = __shfl_up_sync(FULLM, im10, d);
        float om11 = __shfl_up_sync(FULLM, im11, d);
        float ov0  = __shfl_up_sync(FULLM, iv0,  d);
        float ov1  = __shfl_up_sync(FULLM, iv1,  d);
        if (lane >= d) {
            float n00 = im00*om00 + im01*om10;
            float n01 = im00*om01 + im01*om11;
            float n10 = im10*om00 + im11*om10;
            float n11 = im10*om01 + im11*om11;
            float nv0 = im00*ov0 + im01*ov1 + iv0;
            float nv1 = im10*ov0 + im11*ov1 + iv1;
            im00=n00; im01=n01; im10=n10; im11=n11; iv0=nv0; iv1=nv1;
        }
    }
    // exclusive prefix
    float em00 = __shfl_up_sync(FULLM, im00, 1);
    float em01 = __shfl_up_sync(FULLM, im01, 1);
    float em10 = __shfl_up_sync(FULLM, im10, 1);
    float em11 = __shfl_up_sync(FULLM, im11, 1);
    float ev0  = __shfl_up_sync(FULLM, iv0,  1);
    float ev1  = __shfl_up_sync(FULLM, iv1,  1);
    if (lane == 0) { em00 = 1.f; em01 = 0.f; em10 = 0.f; em11 = 1.f; ev0 = 0.f; ev1 = 0.f; }

    float s1 = em00 * ws0 + em01 * ws1 + ev0;
    float s2 = em10 * ws0 + em11 * ws1 + ev1;

    // serial replay of 8 samples
    float4 o1, o2; float yo;
    yo = xa.x - l0a.x*s1 - l0a.y*s2;  s2 = s1; s1 = yo; o1.x = yo;
    yo = xa.y - l0a.z*s1 - l0a.w*s2;  s2 = s1; s1 = yo; o1.y = yo;
    yo = xa.z - l1a.x*s1 - l1a.y*s2;  s2 = s1; s1 = yo; o1.z = yo;
    yo = xa.w - l1a.z*s1 - l1a.w*s2;  s2 = s1; s1 = yo; o1.w = yo;
    yo = xb.x - l0b.x*s1 - l0b.y*s2;  s2 = s1; s1 = yo; o2.x = yo;
    yo = xb.y - l0b.z*s1 - l0b.w*s2;  s2 = s1; s1 = yo; o2.y = yo;
    yo = xb.z - l1b.x*s1 - l1b.y*s2;  s2 = s1; s1 = yo; o2.z = yo;
    yo = xb.w - l1b.z*s1 - l1b.w*s2;  s2 = s1; s1 = yo; o2.w = yo;

    const int Gm = blk * 256 + 64 * wrp + 2 * lane;
    float4* og = reinterpret_cast<float4*>(out + (size_t)b * TLEN);
    if (Gm < T4)     og[Gm]     = o1;
    if (Gm + 1 < T4) og[Gm + 1] = o2;
}

extern "C" void kernel_launch(void* const* d_in, const int* in_sizes, int n_in,
                              void* d_out, int out_size)
{
    const float* y  = (const float*)d_in[0];
    const float* Ae = (const float*)d_in[1];
    const float* Al = (const float*)d_in[2];
    float* out = (float*)d_out;

    diffks_fused<<<BATCH * BPR, TPB>>>(y, Ae, Al, out);
}

// round 9
// speedup vs baseline: 1.4602x; 1.0601x over previous
#include <cuda_runtime.h>
#include <cstdint>

// DiffKS fused: FIR (order 6) + order-2 IIR via warp-parallel affine scan
// (8 samples/thread), with cp.async double-buffered tile pipeline:
// each block processes 4 consecutive 1024-sample tiles, prefetching tile i+1
// into the alternate smem stage while computing tile i (lookahead = full tile
// of compute >> DRAM latency).
//   x[t]  = y[t] + sum_{k=1..6} Ae[t,k-1]*y[t-k]
//   out[t]= x[t] - a1[t]*out[t-1] - a2[t]*out[t-2]
// Warp = 256 samples + 32-sample warm halo from zero state (|a|<=0.25 ->
// contraction ~0.64/step -> ~6e-7). Warp 0 of tile 0 forces exact zero state.
// Pair-granular smem layouts (pitch 13 / 5) -> conflict-free LDS.128.

#define BATCH 48
#define TLEN  88200
#define T4    22050
#define Y_F4_ROW  22050
#define AE_F4_ROW 132300
#define AL_F4_ROW 44100

#define TPB   128
#define TROW  87                  // tiles per row (87*256 f4 >= 22050)
#define NT    4                   // tiles per block
#define BPR   22                  // blocks per row = ceil(87/4)
#define NPAIR 132
#define FULLM 0xffffffffu

// stage layout (float4 units)
#define SY_OFF   0
#define SAE_OFF  268
#define SAL_OFF  (268 + NPAIR * 13)       // 1984
#define STAGE_F4 (SAL_OFF + NPAIR * 5)    // 2644
#define STAGE_BYTES (STAGE_F4 * 16)       // 42304
#define SMEM_BYTES  (2 * STAGE_BYTES)     // 84608

__device__ __forceinline__ void cp16(uint32_t dst, const float4* src) {
    asm volatile("cp.async.ca.shared.global [%0], [%1], 16;" :: "r"(dst), "l"(src));
}
__device__ __forceinline__ void cp_commit() {
    asm volatile("cp.async.commit_group;");
}

__device__ __forceinline__ void map_step(float a1, float a2, float x,
                                         float& m00, float& m01, float& m10,
                                         float& m11, float& v0, float& v1)
{
    float t00 = -(a1*m00 + a2*m10);
    float t01 = -(a1*m01 + a2*m11);
    float tv0 = x - a1*v0 - a2*v1;
    m10 = m00; m11 = m01; v1 = v0;
    m00 = t00; m01 = t01; v0 = tv0;
}

__global__ void __launch_bounds__(TPB, 2)
diffks_fused(const float* __restrict__ y, const float* __restrict__ Ae,
             const float* __restrict__ Al, float* __restrict__ out)
{
    extern __shared__ float4 sm[];

    const int tid  = threadIdx.x;
    const int lane = tid & 31;
    const int wrp  = tid >> 5;
    const int b    = blockIdx.x / BPR;
    const int blkr = blockIdx.x % BPR;
    const int tbeg = blkr * NT;
    const int tend_ = min(tbeg + NT, TROW);

    const float4* yg  = (const float4*)y  + (size_t)b * Y_F4_ROW;
    const float4* aeg = (const float4*)Ae + (size_t)b * AE_F4_ROW;
    const float4* alg = (const float4*)Al + (size_t)b * AL_F4_ROW;
    float4* og = reinterpret_cast<float4*>(out + (size_t)b * TLEN);

    const uint32_t smu = (uint32_t)__cvta_generic_to_shared(sm);

    // ---- issue one tile's staging into stage s (all coalesced cp.async) ----
    auto stage = [&](int tile, int s) {
        const int G0 = tile * 256 - 8;
        const uint32_t sb = smu + (uint32_t)s * STAGE_BYTES;
        #pragma unroll
        for (int j = 0; j < 3; j++) {                  // y: 266 f4
            int f = tid + TPB * j;
            if (f < 266) {
                int gi = min(max(G0 - 2 + f, 0), Y_F4_ROW - 1);
                cp16(sb + (uint32_t)((SY_OFF + f) * 16), yg + gi);
            }
        }
        #pragma unroll
        for (int j = 0; j < 13; j++) {                 // Ae: 1584 f4
            int f = tid + TPB * j;
            if (f < NPAIR * 12) {
                int gi = min(max(G0 * 6 + f, 0), AE_F4_ROW - 1);
                int p = f / 12, k = f - 12 * p;
                cp16(sb + (uint32_t)((SAE_OFF + p * 13 + k) * 16), aeg + gi);
            }
        }
        #pragma unroll
        for (int j = 0; j < 5; j++) {                  // Al: 528 f4
            int f = tid + TPB * j;
            if (f < NPAIR * 4) {
                int gi = min(max(G0 * 2 + f, 0), AL_F4_ROW - 1);
                int p = f >> 2, k = f & 3;
                cp16(sb + (uint32_t)((SAL_OFF + p * 5 + k) * 16), alg + gi);
            }
        }
    };

    // prologue
    stage(tbeg, 0);
    cp_commit();

    for (int tile = tbeg; tile < tend_; tile++) {
        const int s = (tile - tbeg) & 1;
        const bool more = (tile + 1 < tend_);
        if (more) { stage(tile + 1, s ^ 1); cp_commit(); }

        if (more) asm volatile("cp.async.wait_group 1;");
        else      asm volatile("cp.async.wait_group 0;");
        __syncthreads();

        float4* sY  = sm + s * STAGE_F4 + SY_OFF;
        float4* sAe = sm + s * STAGE_F4 + SAE_OFF;
        float4* sAl = sm + s * STAGE_F4 + SAL_OFF;

        if (tile == 0) {               // row start: zero the y halo (G0-2+f < 0)
            if (tid < 10) sY[tid] = make_float4(0.f, 0.f, 0.f, 0.f);
            __syncthreads();
        }

        // FIR for local group g (4 samples)
        auto fir4 = [&](int g, float4& x4, float4& l0, float4& l1) {
            const float4* aeP = &sAe[(g >> 1) * 13 + (g & 1) * 6];
            const float4* alP = &sAl[(g >> 1) * 5  + (g & 1) * 2];
            float4 y4  = sY[g + 2];
            float4 ym1 = sY[g + 1];
            float4 ym2 = sY[g];
            float h0 = ym1.w, h1 = ym1.z, h2 = ym1.y, h3 = ym1.x;
            float h4 = ym2.w, h5 = ym2.z;
            float4 e0 = aeP[0], e1 = aeP[1], e2 = aeP[2];
            float4 e3 = aeP[3], e4 = aeP[4], e5 = aeP[5];
            l0 = alP[0]; l1 = alP[1];

            x4.x = y4.x + e0.x*h0 + e0.y*h1 + e0.z*h2 + e0.w*h3 + e1.x*h4 + e1.y*h5;
            h5=h4; h4=h3; h3=h2; h2=h1; h1=h0; h0=y4.x;
            x4.y = y4.y + e1.z*h0 + e1.w*h1 + e2.x*h2 + e2.y*h3 + e2.z*h4 + e2.w*h5;
            h5=h4; h4=h3; h3=h2; h2=h1; h1=h0; h0=y4.y;
            x4.z = y4.z + e3.x*h0 + e3.y*h1 + e3.z*h2 + e3.w*h3 + e4.x*h4 + e4.y*h5;
            h5=h4; h4=h3; h3=h2; h2=h1; h1=h0; h0=y4.z;
            x4.w = y4.w + e4.z*h0 + e4.w*h1 + e5.x*h2 + e5.y*h3 + e5.z*h4 + e5.w*h5;
        };

        // ---- warm sub-scan (lanes 0-7) ----
        float wm00 = 1.f, wm01 = 0.f, wm10 = 0.f, wm11 = 1.f, wv0 = 0.f, wv1 = 0.f;
        if (lane < 8) {
            float4 wx4, wl0, wl1;
            fir4(64 * wrp + lane, wx4, wl0, wl1);
            wm00 = -wl0.x; wm01 = -wl0.y; wm10 = 1.f; wm11 = 0.f; wv0 = wx4.x; wv1 = 0.f;
            map_step(wl0.z, wl0.w, wx4.y, wm00, wm01, wm10, wm11, wv0, wv1);
            map_step(wl1.x, wl1.y, wx4.z, wm00, wm01, wm10, wm11, wv0, wv1);
            map_step(wl1.z, wl1.w, wx4.w, wm00, wm01, wm10, wm11, wv0, wv1);
        }
        #pragma unroll
        for (int d = 1; d <= 4; d <<= 1) {
            float om00 = __shfl_up_sync(FULLM, wm00, d);
            float om01 = __shfl_up_sync(FULLM, wm01, d);
            float om10 = __shfl_up_sync(FULLM, wm10, d);
            float om11 = __shfl_up_sync(FULLM, wm11, d);
            float ov0  = __shfl_up_sync(FULLM, wv0,  d);
            float ov1  = __shfl_up_sync(FULLM, wv1,  d);
            if (lane >= d) {
                float n00 = wm00*om00 + wm01*om10;
                float n01 = wm00*om01 + wm01*om11;
                float n10 = wm10*om00 + wm11*om10;
                float n11 = wm10*om01 + wm11*om11;
                float nv0 = wm00*ov0 + wm01*ov1 + wv0;
                float nv1 = wm10*ov0 + wm11*ov1 + wv1;
                wm00=n00; wm01=n01; wm10=n10; wm11=n11; wv0=nv0; wv1=nv1;
            }
        }
        float ws0 = __shfl_sync(FULLM, wv0, 7);
        float ws1 = __shfl_sync(FULLM, wv1, 7);
        if (tile == 0 && wrp == 0) { ws0 = 0.f; ws1 = 0.f; }  // exact at t = 0

        // ---- main: 2 groups / thread ----
        const int g0 = 8 + 64 * wrp + 2 * lane;
        float4 xa, l0a, l1a, xb, l0b, l1b;
        fir4(g0,     xa, l0a, l1a);
        fir4(g0 + 1, xb, l0b, l1b);

        float m00 = -l0a.x, m01 = -l0a.y, m10 = 1.f, m11 = 0.f, v0 = xa.x, v1 = 0.f;
        map_step(l0a.z, l0a.w, xa.y, m00, m01, m10, m11, v0, v1);
        map_step(l1a.x, l1a.y, xa.z, m00, m01, m10, m11, v0, v1);
        map_step(l1a.z, l1a.w, xa.w, m00, m01, m10, m11, v0, v1);
        map_step(l0b.x, l0b.y, xb.x, m00, m01, m10, m11, v0, v1);
        map_step(l0b.z, l0b.w, xb.y, m00, m01, m10, m11, v0, v1);
        map_step(l1b.x, l1b.y, xb.z, m00, m01, m10, m11, v0, v1);
        map_step(l1b.z, l1b.w, xb.w, m00, m01, m10, m11, v0, v1);

        float im00 = m00, im01 = m01, im10 = m10, im11 = m11, iv0 = v0, iv1 = v1;
        #pragma unroll
        for (int d = 1; d <= 16; d <<= 1) {
            float om00 = __shfl_up_sync(FULLM, im00, d);
            float om01 = __shfl_up_sync(FULLM, im01, d);
            float om10 = __shfl_up_sync(FULLM, im10, d);
            float om11 = __shfl_up_sync(FULLM, im11, d);
            float ov0  = __shfl_up_sync(FULLM, iv0,  d);
            float ov1  = __shfl_up_sync(FULLM, iv1,  d);
            if (lane >= d) {
                float n00 = im00*om00 + im01*om10;
                float n01 = im00*om01 + im01*om11;
                float n10 = im10*om00 + im11*om10;
                float n11 = im10*om01 + im11*om11;
                float nv0 = im00*ov0 + im01*ov1 + iv0;
                float nv1 = im10*ov0 + im11*ov1 + iv1;
                im00=n00; im01=n01; im10=n10; im11=n11; iv0=nv0; iv1=nv1;
            }
        }
        float em00 = __shfl_up_sync(FULLM, im00, 1);
        float em01 = __shfl_up_sync(FULLM, im01, 1);
        float em10 = __shfl_up_sync(FULLM, im10, 1);
        float em11 = __shfl_up_sync(FULLM, im11, 1);
        float ev0  = __shfl_up_sync(FULLM, iv0,  1);
        float ev1  = __shfl_up_sync(FULLM, iv1,  1);
        if (lane == 0) { em00 = 1.f; em01 = 0.f; em10 = 0.f; em11 = 1.f; ev0 = 0.f; ev1 = 0.f; }

        float s1 = em00 * ws0 + em01 * ws1 + ev0;
        float s2 = em10 * ws0 + em11 * ws1 + ev1;

        float4 o1, o2; float yo;
        yo = xa.x - l0a.x*s1 - l0a.y*s2;  s2 = s1; s1 = yo; o1.x = yo;
        yo = xa.y - l0a.z*s1 - l0a.w*s2;  s2 = s1; s1 = yo; o1.y = yo;
        yo = xa.z - l1a.x*s1 - l1a.y*s2;  s2 = s1; s1 = yo; o1.z = yo;
        yo = xa.w - l1a.z*s1 - l1a.w*s2;  s2 = s1; s1 = yo; o1.w = yo;
        yo = xb.x - l0b.x*s1 - l0b.y*s2;  s2 = s1; s1 = yo; o2.x = yo;
        yo = xb.y - l0b.z*s1 - l0b.w*s2;  s2 = s1; s1 = yo; o2.y = yo;
        yo = xb.z - l1b.x*s1 - l1b.y*s2;  s2 = s1; s1 = yo; o2.z = yo;
        yo = xb.w - l1b.z*s1 - l1b.w*s2;  s2 = s1; s1 = yo; o2.w = yo;

        const int Gm = tile * 256 + 64 * wrp + 2 * lane;
        if (Gm < T4)     og[Gm]     = o1;
        if (Gm + 1 < T4) og[Gm + 1] = o2;

        __syncthreads();    // all reads of stage s done before it is refilled
    }
}

extern "C" void kernel_launch(void* const* d_in, const int* in_sizes, int n_in,
                              void* d_out, int out_size)
{
    const float* y  = (const float*)d_in[0];
    const float* Ae = (const float*)d_in[1];
    const float* Al = (const float*)d_in[2];
    float* out = (float*)d_out;

    cudaFuncSetAttribute(diffks_fused,
                         cudaFuncAttributeMaxDynamicSharedMemorySize, SMEM_BYTES);

    diffks_fused<<<BATCH * BPR, TPB, SMEM_BYTES>>>(y, Ae, Al, out);
}

// round 10
// speedup vs baseline: 1.5195x; 1.0406x over previous
#include <cuda_runtime.h>
#include <cstdint>

// DiffKS fused: FIR (order 6) + order-2 IIR via warp-parallel affine scan
// (8 samples/thread), cp.async double-buffered tile pipeline, flat tile list.
//   x[t]  = y[t] + sum_{k=1..6} Ae[t,k-1]*y[t-k]
//   out[t]= x[t] - a1[t]*out[t-1] - a2[t]*out[t-2]
// Warp = 256 samples + 32-sample warm halo from zero state (|a|<=0.25 ->
// contraction ~0.64/step -> ~6e-7). Tile 0 of each row: exact zero state.
// R9 lesson: 2 CTAs/SM (84.6KB smem) can't hide SHFL-chain + mem latency.
// This version: Al moved out of smem to direct per-thread LDG.128 (contiguous
// 64B/thread) with register double-buffer prefetch -> stage 31.7KB -> 3 CTAs/SM;
// grid = 444 = exactly one 3-CTA wave, 9-10 tiles per block.

#define BATCH 48
#define TLEN  88200
#define T4    22050
#define Y_F4_ROW  22050
#define AE_F4_ROW 132300
#define AL_F4_ROW 44100

#define TPB    128
#define TROW   87                 // tiles per row (87*256 f4 >= 22050)
#define NTILES (BATCH * TROW)     // 4176
#define GRID   444                // 148 SM * 3 CTAs = single wave
#define NPAIR  132
#define FULLM  0xffffffffu

// stage layout (float4 units): y + Ae only
#define SY_OFF   0
#define SAE_OFF  268
#define STAGE_F4 (268 + NPAIR * 13)       // 1984
#define STAGE_BYTES (STAGE_F4 * 16)       // 31744
#define SMEM_BYTES  (2 * STAGE_BYTES)     // 63488

__device__ __forceinline__ void cp16(uint32_t dst, const float4* src) {
    asm volatile("cp.async.ca.shared.global [%0], [%1], 16;" :: "r"(dst), "l"(src));
}
__device__ __forceinline__ void cp_commit() {
    asm volatile("cp.async.commit_group;");
}

__device__ __forceinline__ void map_step(float a1, float a2, float x,
                                         float& m00, float& m01, float& m10,
                                         float& m11, float& v0, float& v1)
{
    float t00 = -(a1*m00 + a2*m10);
    float t01 = -(a1*m01 + a2*m11);
    float tv0 = x - a1*v0 - a2*v1;
    m10 = m00; m11 = m01; v1 = v0;
    m00 = t00; m01 = t01; v0 = tv0;
}

struct AlRegs { float4 w0, w1, a0, a1, a2, a3; };

__global__ void __launch_bounds__(TPB, 3)
diffks_fused(const float* __restrict__ y, const float* __restrict__ Ae,
             const float* __restrict__ Al, float* __restrict__ out)
{
    extern __shared__ float4 sm[];

    const int tid  = threadIdx.x;
    const int lane = tid & 31;
    const int wrp  = tid >> 5;

    // flat balanced tile partition
    const int t0 = (int)(((long long)blockIdx.x * NTILES) / GRID);
    const int t1 = (int)(((long long)(blockIdx.x + 1) * NTILES) / GRID);

    const uint32_t smu = (uint32_t)__cvta_generic_to_shared(sm);

    // ---- stage tile tau's y + Ae into stage s (coalesced cp.async) ----
    auto stage = [&](int tau, int s) {
        int br = tau / TROW, tr = tau - br * TROW;
        const float4* yg  = (const float4*)y  + (size_t)br * Y_F4_ROW;
        const float4* aeg = (const float4*)Ae + (size_t)br * AE_F4_ROW;
        const int G0 = tr * 256 - 8;
        const uint32_t sb = smu + (uint32_t)s * STAGE_BYTES;
        #pragma unroll
        for (int j = 0; j < 3; j++) {                  // y: 266 f4
            int f = tid + TPB * j;
            if (f < 266) {
                int gi = min(max(G0 - 2 + f, 0), Y_F4_ROW - 1);
                cp16(sb + (uint32_t)((SY_OFF + f) * 16), yg + gi);
            }
        }
        #pragma unroll
        for (int j = 0; j < 13; j++) {                 // Ae: 1584 f4, pitch-13 pairs
            int f = tid + TPB * j;
            if (f < NPAIR * 12) {
                int gi = min(max(G0 * 6 + f, 0), AE_F4_ROW - 1);
                int p = f / 12, k = f - 12 * p;
                cp16(sb + (uint32_t)((SAE_OFF + p * 13 + k) * 16), aeg + gi);
            }
        }
    };

    // ---- per-thread direct Al loads for tile tau (contiguous 64B/thread) ----
    auto load_al = [&](int tau) {
        AlRegs r;
        int br = tau / TROW, tr = tau - br * TROW;
        const float4* alg = (const float4*)Al + (size_t)br * AL_F4_ROW;
        int gw = tr * 256 - 8 + 64 * wrp + (lane & 7);       // warm group
        int iw = min(max(2 * gw, 0), AL_F4_ROW - 2);
        r.w0 = alg[iw]; r.w1 = alg[iw + 1];
        int gm = tr * 256 + 64 * wrp + 2 * lane;             // first main group
        int im = min(2 * gm, AL_F4_ROW - 4);
        r.a0 = alg[im];     r.a1 = alg[im + 1];
        r.a2 = alg[im + 2]; r.a3 = alg[im + 3];
        return r;
    };

    // prologue
    stage(t0, 0);
    cp_commit();
    AlRegs alc = load_al(t0);

    for (int k = t0; k < t1; k++) {
        const int s = (k - t0) & 1;
        const bool more = (k + 1 < t1);
        if (more) { stage(k + 1, s ^ 1); cp_commit(); }
        AlRegs aln;
        if (more) aln = load_al(k + 1);

        if (more) asm volatile("cp.async.wait_group 1;");
        else      asm volatile("cp.async.wait_group 0;");
        __syncthreads();

        const int br = k / TROW, tr = k - br * TROW;
        float4* sY  = sm + s * STAGE_F4 + SY_OFF;
        float4* sAe = sm + s * STAGE_F4 + SAE_OFF;

        if (tr == 0) {               // row start: zero the y halo
            if (tid < 10) sY[tid] = make_float4(0.f, 0.f, 0.f, 0.f);
            __syncthreads();
        }

        // FIR for local group g (4 samples) from staged y/Ae
        auto fir4 = [&](int g, float4& x4) {
            const float4* aeP = &sAe[(g >> 1) * 13 + (g & 1) * 6];
            float4 y4  = sY[g + 2];
            float4 ym1 = sY[g + 1];
            float4 ym2 = sY[g];
            float h0 = ym1.w, h1 = ym1.z, h2 = ym1.y, h3 = ym1.x;
            float h4 = ym2.w, h5 = ym2.z;
            float4 e0 = aeP[0], e1 = aeP[1], e2 = aeP[2];
            float4 e3 = aeP[3], e4 = aeP[4], e5 = aeP[5];

            x4.x = y4.x + e0.x*h0 + e0.y*h1 + e0.z*h2 + e0.w*h3 + e1.x*h4 + e1.y*h5;
            h5=h4; h4=h3; h3=h2; h2=h1; h1=h0; h0=y4.x;
            x4.y = y4.y + e1.z*h0 + e1.w*h1 + e2.x*h2 + e2.y*h3 + e2.z*h4 + e2.w*h5;
            h5=h4; h4=h3; h3=h2; h2=h1; h1=h0; h0=y4.y;
            x4.z = y4.z + e3.x*h0 + e3.y*h1 + e3.z*h2 + e3.w*h3 + e4.x*h4 + e4.y*h5;
            h5=h4; h4=h3; h3=h2; h2=h1; h1=h0; h0=y4.z;
            x4.w = y4.w + e4.z*h0 + e4.w*h1 + e5.x*h2 + e5.y*h3 + e5.z*h4 + e5.w*h5;
        };

        // ---- warm sub-scan (lanes 0-7, one group each) ----
        float wm00 = 1.f, wm01 = 0.f, wm10 = 0.f, wm11 = 1.f, wv0 = 0.f, wv1 = 0.f;
        if (lane < 8) {
            float4 wx4;
            fir4(64 * wrp + lane, wx4);
            wm00 = -alc.w0.x; wm01 = -alc.w0.y; wm10 = 1.f; wm11 = 0.f;
            wv0 = wx4.x; wv1 = 0.f;
            map_step(alc.w0.z, alc.w0.w, wx4.y, wm00, wm01, wm10, wm11, wv0, wv1);
            map_step(alc.w1.x, alc.w1.y, wx4.z, wm00, wm01, wm10, wm11, wv0, wv1);
            map_step(alc.w1.z, alc.w1.w, wx4.w, wm00, wm01, wm10, wm11, wv0, wv1);
        }
        #pragma unroll
        for (int d = 1; d <= 4; d <<= 1) {
            float om00 = __shfl_up_sync(FULLM, wm00, d);
            float om01 = __shfl_up_sync(FULLM, wm01, d);
            float om10 = __shfl_up_sync(FULLM, wm10, d);
            float om11 = __shfl_up_sync(FULLM, wm11, d);
            float ov0  = __shfl_up_sync(FULLM, wv0,  d);
            float ov1  = __shfl_up_sync(FULLM, wv1,  d);
            if (lane >= d) {
                float n00 = wm00*om00 + wm01*om10;
                float n01 = wm00*om01 + wm01*om11;
                float n10 = wm10*om00 + wm11*om10;
                float n11 = wm10*om01 + wm11*om11;
                float nv0 = wm00*ov0 + wm01*ov1 + wv0;
                float nv1 = wm10*ov0 + wm11*ov1 + wv1;
                wm00=n00; wm01=n01; wm10=n10; wm11=n11; wv0=nv0; wv1=nv1;
            }
        }
        float ws0 = __shfl_sync(FULLM, wv0, 7);
        float ws1 = __shfl_sync(FULLM, wv1, 7);
        if (tr == 0 && wrp == 0) { ws0 = 0.f; ws1 = 0.f; }   // exact at t = 0

        // ---- main: 2 groups / thread, 8-step map ----
        const int g0 = 8 + 64 * wrp + 2 * lane;
        float4 xa, xb;
        fir4(g0,     xa);
        fir4(g0 + 1, xb);
        const float4 l0a = alc.a0, l1a = alc.a1, l0b = alc.a2, l1b = alc.a3;

        float m00 = -l0a.x, m01 = -l0a.y, m10 = 1.f, m11 = 0.f, v0 = xa.x, v1 = 0.f;
        map_step(l0a.z, l0a.w, xa.y, m00, m01, m10, m11, v0, v1);
        map_step(l1a.x, l1a.y, xa.z, m00, m01, m10, m11, v0, v1);
        map_step(l1a.z, l1a.w, xa.w, m00, m01, m10, m11, v0, v1);
        map_step(l0b.x, l0b.y, xb.x, m00, m01, m10, m11, v0, v1);
        map_step(l0b.z, l0b.w, xb.y, m00, m01, m10, m11, v0, v1);
        map_step(l1b.x, l1b.y, xb.z, m00, m01, m10, m11, v0, v1);
        map_step(l1b.z, l1b.w, xb.w, m00, m01, m10, m11, v0, v1);

        float im00 = m00, im01 = m01, im10 = m10, im11 = m11, iv0 = v0, iv1 = v1;
        #pragma unroll
        for (int d = 1; d <= 16; d <<= 1) {
            float om00 = __shfl_up_sync(FULLM, im00, d);
            float om01 = __shfl_up_sync(FULLM, im01, d);
            float om10 = __shfl_up_sync(FULLM, im10, d);
            float om11 = __shfl_up_sync(FULLM, im11, d);
            float ov0  = __shfl_up_sync(FULLM, iv0,  d);
            float ov1  = __shfl_up_sync(FULLM, iv1,  d);
            if (lane >= d) {
                float n00 = im00*om00 + im01*om10;
                float n01 = im00*om01 + im01*om11;
                float n10 = im10*om00 + im11*om10;
                float n11 = im10*om01 + im11*om11;
                float nv0 = im00*ov0 + im01*ov1 + iv0;
                float nv1 = im10*ov0 + im11*ov1 + iv1;
                im00=n00; im01=n01; im10=n10; im11=n11; iv0=nv0; iv1=nv1;
            }
        }
        float em00 = __shfl_up_sync(FULLM, im00, 1);
        float em01 = __shfl_up_sync(FULLM, im01, 1);
        float em10 = __shfl_up_sync(FULLM, im10, 1);
        float em11 = __shfl_up_sync(FULLM, im11, 1);
        float ev0  = __shfl_up_sync(FULLM, iv0,  1);
        float ev1  = __shfl_up_sync(FULLM, iv1,  1);
        if (lane == 0) { em00 = 1.f; em01 = 0.f; em10 = 0.f; em11 = 1.f; ev0 = 0.f; ev1 = 0.f; }

        float s1 = em00 * ws0 + em01 * ws1 + ev0;
        float s2 = em10 * ws0 + em11 * ws1 + ev1;

        float4 o1, o2; float yo;
        yo = xa.x - l0a.x*s1 - l0a.y*s2;  s2 = s1; s1 = yo; o1.x = yo;
        yo = xa.y - l0a.z*s1 - l0a.w*s2;  s2 = s1; s1 = yo; o1.y = yo;
        yo = xa.z - l1a.x*s1 - l1a.y*s2;  s2 = s1; s1 = yo; o1.z = yo;
        yo = xa.w - l1a.z*s1 - l1a.w*s2;  s2 = s1; s1 = yo; o1.w = yo;
        yo = xb.x - l0b.x*s1 - l0b.y*s2;  s2 = s1; s1 = yo; o2.x = yo;
        yo = xb.y - l0b.z*s1 - l0b.w*s2;  s2 = s1; s1 = yo; o2.y = yo;
        yo = xb.z - l1b.x*s1 - l1b.y*s2;  s2 = s1; s1 = yo; o2.z = yo;
        yo = xb.w - l1b.z*s1 - l1b.w*s2;  s2 = s1; s1 = yo; o2.w = yo;

        float4* og = reinterpret_cast<float4*>(out + (size_t)br * TLEN);
        const int Gm = tr * 256 + 64 * wrp + 2 * lane;
        if (Gm < T4)     og[Gm]     = o1;
        if (Gm + 1 < T4) og[Gm + 1] = o2;

        __syncthreads();          // stage s fully read before refill next iter
        alc = aln;
    }
}

extern "C" void kernel_launch(void* const* d_in, const int* in_sizes, int n_in,
                              void* d_out, int out_size)
{
    const float* y  = (const float*)d_in[0];
    const float* Ae = (const float*)d_in[1];
    const float* Al = (const float*)d_in[2];
    float* out = (float*)d_out;

    cudaFuncSetAttribute(diffks_fused,
                         cudaFuncAttributeMaxDynamicSharedMemorySize, SMEM_BYTES);

    diffks_fused<<<GRID, TPB, SMEM_BYTES>>>(y, Ae, Al, out);
}

// round 11
// speedup vs baseline: 1.5548x; 1.0233x over previous
#include <cuda_runtime.h>
#include <cstdint>

// DiffKS fused: FIR (order 6) + order-2 IIR via warp affine scan (8 samples/
// thread) + BLOCK-level scan with exact cross-tile state chaining.
//   x[t]  = y[t] + sum_{k=1..6} Ae[t,k-1]*y[t-k]
//   out[t]= x[t] - a1[t]*out[t-1] - a2[t]*out[t-2]
// Each block owns ~9 consecutive 1024-sample tiles (cp.async double-buffered).
// Per tile: warps build 8-sample affine maps, 5-round lane scan -> lane-31
// composite stored to smem; warps fold wm[0..w-1] into the block-carried IIR
// state for EXACT warp entry states (no per-tile warmup). Block state chains
// across tiles; row starts (tr==0) reset it to exact zero. Only a mid-row
// block start runs one 32-sample warmup (|a|<=0.25 -> ~0.64/step -> ~6e-7).

#define BATCH 48
#define TLEN  88200
#define T4    22050
#define Y_F4_ROW  22050
#define AE_F4_ROW 132300
#define AL_F4_ROW 44100

#define TPB    128
#define TROW   87                    // tiles per row
#define NTILES (BATCH * TROW)        // 4176
#define GRID   444                   // 148 SMs * 3 CTAs = single wave
#define FULLM  0xffffffffu

// stage layout (float4): y 260 (258 used) + Ae 128 pairs * pitch 13
#define SY_OFF   0
#define SAE_OFF  260
#define STAGE_F4 (260 + 128 * 13)            // 1924
#define STAGE_BYTES (STAGE_F4 * 16)          // 30784
#define SMEM_BYTES  (2 * STAGE_BYTES)        // 61568  (3 CTAs/SM)

__device__ __forceinline__ void cp16(uint32_t dst, const float4* src) {
    asm volatile("cp.async.ca.shared.global [%0], [%1], 16;" :: "r"(dst), "l"(src));
}
__device__ __forceinline__ void cp16z(uint32_t dst, const float4* src, int sz) {
    asm volatile("cp.async.ca.shared.global [%0], [%1], 16, %2;"
                 :: "r"(dst), "l"(src), "r"(sz));
}
__device__ __forceinline__ void cp_commit() {
    asm volatile("cp.async.commit_group;");
}

__device__ __forceinline__ void map_step(float a1, float a2, float x,
                                         float& m00, float& m01, float& m10,
                                         float& m11, float& v0, float& v1)
{
    float t00 = -(a1*m00 + a2*m10);
    float t01 = -(a1*m01 + a2*m11);
    float tv0 = x - a1*v0 - a2*v1;
    m10 = m00; m11 = m01; v1 = v0;
    m00 = t00; m01 = t01; v0 = tv0;
}

struct AlRegs { float4 a0, a1, a2, a3; };

__global__ void __launch_bounds__(TPB, 3)
diffks_fused(const float* __restrict__ y, const float* __restrict__ Ae,
             const float* __restrict__ Al, float* __restrict__ out)
{
    extern __shared__ float4 sm[];
    __shared__ float wm[4][6];       // per-warp composite maps

    const int tid  = threadIdx.x;
    const int lane = tid & 31;
    const int wrp  = tid >> 5;

    const int t0 = (int)(((long long)blockIdx.x * NTILES) / GRID);
    const int t1 = (int)(((long long)(blockIdx.x + 1) * NTILES) / GRID);

    const uint32_t smu = (uint32_t)__cvta_generic_to_shared(sm);

    // ---- stage tile tau's y + Ae into stage s ----
    auto stage = [&](int tau, int s) {
        int br = tau / TROW, tr = tau - br * TROW;
        const float4* yg  = (const float4*)y  + (size_t)br * Y_F4_ROW;
        const float4* aeg = (const float4*)Ae + (size_t)br * AE_F4_ROW;
        const uint32_t sb = smu + (uint32_t)s * STAGE_BYTES;
        #pragma unroll
        for (int j = 0; j < 3; j++) {                  // y: 258 f4 (halo -2)
            int f = tid + TPB * j;
            if (f < 258) {
                int gi = tr * 256 - 2 + f;
                int gc = min(max(gi, 0), Y_F4_ROW - 1);
                cp16z(sb + (uint32_t)((SY_OFF + f) * 16), yg + gc, (gi < 0) ? 0 : 16);
            }
        }
        #pragma unroll
        for (int j = 0; j < 12; j++) {                 // Ae: 1536 f4, pitch-13 pairs
            int f = tid + TPB * j;
            int gi = min(tr * 1536 + f, AE_F4_ROW - 1);
            int p = f / 12, k = f - 12 * p;
            cp16(sb + (uint32_t)((SAE_OFF + p * 13 + k) * 16), aeg + gi);
        }
    };

    // ---- per-thread direct Al loads (4 contiguous f4) ----
    auto load_al = [&](int tau) {
        AlRegs r;
        int br = tau / TROW, tr = tau - br * TROW;
        const float4* alg = (const float4*)Al + (size_t)br * AL_F4_ROW;
        int gm = tr * 256 + 64 * wrp + 2 * lane;
        int im = min(2 * gm, AL_F4_ROW - 4);
        r.a0 = alg[im];     r.a1 = alg[im + 1];
        r.a2 = alg[im + 2]; r.a3 = alg[im + 3];
        return r;
    };

    // ---- prologue: start memory first ----
    stage(t0, 0);
    cp_commit();
    AlRegs alc = load_al(t0);

    // ---- block entry state: exact zero at row start, else one-time warmup ----
    float bs0 = 0.f, bs1 = 0.f;
    {
        int br0 = t0 / TROW, tr0 = t0 - br0 * TROW;
        if (tr0 != 0) {
            const float4* ygw  = (const float4*)y  + (size_t)br0 * Y_F4_ROW;
            const float4* aegw = (const float4*)Ae + (size_t)br0 * AE_F4_ROW;
            const float4* algw = (const float4*)Al + (size_t)br0 * AL_F4_ROW;
            int W  = tr0 * 256 - 8 + lane;                 // warm group (lanes 0-7 used)
            int Wc = min(W, Y_F4_ROW - 1);
            float4 yv  = ygw[Wc];
            float4 yv1 = ygw[Wc - 1];
            float4 yv2 = ygw[Wc - 2];
            int ai = min(6 * W, AE_F4_ROW - 6);
            float4 e0 = aegw[ai],     e1 = aegw[ai + 1], e2 = aegw[ai + 2];
            float4 e3 = aegw[ai + 3], e4 = aegw[ai + 4], e5 = aegw[ai + 5];
            int li = min(2 * W, AL_F4_ROW - 2);
            float4 l0 = algw[li], l1 = algw[li + 1];

            float h0 = yv1.w, h1 = yv1.z, h2 = yv1.y, h3 = yv1.x;
            float h4 = yv2.w, h5 = yv2.z;
            float4 x4;
            x4.x = yv.x + e0.x*h0 + e0.y*h1 + e0.z*h2 + e0.w*h3 + e1.x*h4 + e1.y*h5;
            h5=h4; h4=h3; h3=h2; h2=h1; h1=h0; h0=yv.x;
            x4.y = yv.y + e1.z*h0 + e1.w*h1 + e2.x*h2 + e2.y*h3 + e2.z*h4 + e2.w*h5;
            h5=h4; h4=h3; h3=h2; h2=h1; h1=h0; h0=yv.y;
            x4.z = yv.z + e3.x*h0 + e3.y*h1 + e3.z*h2 + e3.w*h3 + e4.x*h4 + e4.y*h5;
            h5=h4; h4=h3; h3=h2; h2=h1; h1=h0; h0=yv.z;
            x4.w = yv.w + e4.z*h0 + e4.w*h1 + e5.x*h2 + e5.y*h3 + e5.z*h4 + e5.w*h5;

            float m00 = -l0.x, m01 = -l0.y, m10 = 1.f, m11 = 0.f, v0 = x4.x, v1 = 0.f;
            map_step(l0.z, l0.w, x4.y, m00, m01, m10, m11, v0, v1);
            map_step(l1.x, l1.y, x4.z, m00, m01, m10, m11, v0, v1);
            map_step(l1.z, l1.w, x4.w, m00, m01, m10, m11, v0, v1);
            #pragma unroll
            for (int d = 1; d <= 4; d <<= 1) {
                float om00 = __shfl_up_sync(FULLM, m00, d);
                float om01 = __shfl_up_sync(FULLM, m01, d);
                float om10 = __shfl_up_sync(FULLM, m10, d);
                float om11 = __shfl_up_sync(FULLM, m11, d);
                float ov0  = __shfl_up_sync(FULLM, v0,  d);
                float ov1  = __shfl_up_sync(FULLM, v1,  d);
                if (lane >= d) {
                    float n00 = m00*om00 + m01*om10;
                    float n01 = m00*om01 + m01*om11;
                    float n10 = m10*om00 + m11*om10;
                    float n11 = m10*om01 + m11*om11;
                    float nv0 = m00*ov0 + m01*ov1 + v0;
                    float nv1 = m10*ov0 + m11*ov1 + v1;
                    m00=n00; m01=n01; m10=n10; m11=n11; v0=nv0; v1=nv1;
                }
            }
            bs0 = __shfl_sync(FULLM, v0, 7);
            bs1 = __shfl_sync(FULLM, v1, 7);
        }
    }

    AlRegs aln = alc;

    for (int k = t0; k < t1; k++) {
        const int s = (k - t0) & 1;
        const bool more = (k + 1 < t1);
        if (more) { stage(k + 1, s ^ 1); cp_commit(); aln = load_al(k + 1); }

        if (more) asm volatile("cp.async.wait_group 1;");
        else      asm volatile("cp.async.wait_group 0;");
        __syncthreads();                       // (1) stage ready; prev wm reads done

        const int br = k / TROW, tr = k - br * TROW;
        if (tr == 0) { bs0 = 0.f; bs1 = 0.f; } // exact zero state at row start

        const float4* sY  = sm + s * STAGE_F4 + SY_OFF;
        const float4* sAe = sm + s * STAGE_F4 + SAE_OFF;

        auto fir4 = [&](int g, float4& x4) {
            const float4* aeP = &sAe[(g >> 1) * 13 + (g & 1) * 6];
            float4 y4  = sY[g + 2];
            float4 ym1 = sY[g + 1];
            float4 ym2 = sY[g];
            float h0 = ym1.w, h1 = ym1.z, h2 = ym1.y, h3 = ym1.x;
            float h4 = ym2.w, h5 = ym2.z;
            float4 e0 = aeP[0], e1 = aeP[1], e2 = aeP[2];
            float4 e3 = aeP[3], e4 = aeP[4], e5 = aeP[5];
            x4.x = y4.x + e0.x*h0 + e0.y*h1 + e0.z*h2 + e0.w*h3 + e1.x*h4 + e1.y*h5;
            h5=h4; h4=h3; h3=h2; h2=h1; h1=h0; h0=y4.x;
            x4.y = y4.y + e1.z*h0 + e1.w*h1 + e2.x*h2 + e2.y*h3 + e2.z*h4 + e2.w*h5;
            h5=h4; h4=h3; h3=h2; h2=h1; h1=h0; h0=y4.y;
            x4.z = y4.z + e3.x*h0 + e3.y*h1 + e3.z*h2 + e3.w*h3 + e4.x*h4 + e4.y*h5;
            h5=h4; h4=h3; h3=h2; h2=h1; h1=h0; h0=y4.z;
            x4.w = y4.w + e4.z*h0 + e4.w*h1 + e5.x*h2 + e5.y*h3 + e5.z*h4 + e5.w*h5;
        };

        // ---- FIR + 8-step map ----
        const int g0 = 64 * wrp + 2 * lane;
        float4 xa, xb;
        fir4(g0,     xa);
        fir4(g0 + 1, xb);
        const float4 l0a = alc.a0, l1a = alc.a1, l0b = alc.a2, l1b = alc.a3;

        float m00 = -l0a.x, m01 = -l0a.y, m10 = 1.f, m11 = 0.f, v0 = xa.x, v1 = 0.f;
        map_step(l0a.z, l0a.w, xa.y, m00, m01, m10, m11, v0, v1);
        map_step(l1a.x, l1a.y, xa.z, m00, m01, m10, m11, v0, v1);
        map_step(l1a.z, l1a.w, xa.w, m00, m01, m10, m11, v0, v1);
        map_step(l0b.x, l0b.y, xb.x, m00, m01, m10, m11, v0, v1);
        map_step(l0b.z, l0b.w, xb.y, m00, m01, m10, m11, v0, v1);
        map_step(l1b.x, l1b.y, xb.z, m00, m01, m10, m11, v0, v1);
        map_step(l1b.z, l1b.w, xb.w, m00, m01, m10, m11, v0, v1);

        // ---- 32-lane inclusive scan ----
        float im00 = m00, im01 = m01, im10 = m10, im11 = m11, iv0 = v0, iv1 = v1;
        #pragma unroll
        for (int d = 1; d <= 16; d <<= 1) {
            float om00 = __shfl_up_sync(FULLM, im00, d);
            float om01 = __shfl_up_sync(FULLM, im01, d);
            float om10 = __shfl_up_sync(FULLM, im10, d);
            float om11 = __shfl_up_sync(FULLM, im11, d);
            float ov0  = __shfl_up_sync(FULLM, iv0,  d);
            float ov1  = __shfl_up_sync(FULLM, iv1,  d);
            if (lane >= d) {
                float n00 = im00*om00 + im01*om10;
                float n01 = im00*om01 + im01*om11;
                float n10 = im10*om00 + im11*om10;
                float n11 = im10*om01 + im11*om11;
                float nv0 = im00*ov0 + im01*ov1 + iv0;
                float nv1 = im10*ov0 + im11*ov1 + iv1;
                im00=n00; im01=n01; im10=n10; im11=n11; iv0=nv0; iv1=nv1;
            }
        }
        // warp composite map -> smem (lane 31 holds it)
        if (lane == 31) {
            wm[wrp][0] = im00; wm[wrp][1] = im01; wm[wrp][2] = im10;
            wm[wrp][3] = im11; wm[wrp][4] = iv0;  wm[wrp][5] = iv1;
        }
        // exclusive prefix
        float em00 = __shfl_up_sync(FULLM, im00, 1);
        float em01 = __shfl_up_sync(FULLM, im01, 1);
        float em10 = __shfl_up_sync(FULLM, im10, 1);
        float em11 = __shfl_up_sync(FULLM, im11, 1);
        float ev0  = __shfl_up_sync(FULLM, iv0,  1);
        float ev1  = __shfl_up_sync(FULLM, iv1,  1);
        if (lane == 0) { em00 = 1.f; em01 = 0.f; em10 = 0.f; em11 = 1.f; ev0 = 0.f; ev1 = 0.f; }

        __syncthreads();                       // (2) wm visible; stage reads done

        // warp entry state: fold block state through wm[0..wrp-1]
        float s1w = bs0, s2w = bs1;
        #pragma unroll
        for (int j = 0; j < 3; j++) {
            if (wrp > j) {
                float n1 = wm[j][0]*s1w + wm[j][1]*s2w + wm[j][4];
                float n2 = wm[j][2]*s1w + wm[j][3]*s2w + wm[j][5];
                s1w = n1; s2w = n2;
            }
        }
        float s1 = em00 * s1w + em01 * s2w + ev0;
        float s2 = em10 * s1w + em11 * s2w + ev1;

        // ---- replay 8 samples ----
        float4 o1, o2; float yo;
        yo = xa.x - l0a.x*s1 - l0a.y*s2;  s2 = s1; s1 = yo; o1.x = yo;
        yo = xa.y - l0a.z*s1 - l0a.w*s2;  s2 = s1; s1 = yo; o1.y = yo;
        yo = xa.z - l1a.x*s1 - l1a.y*s2;  s2 = s1; s1 = yo; o1.z = yo;
        yo = xa.w - l1a.z*s1 - l1a.w*s2;  s2 = s1; s1 = yo; o1.w = yo;
        yo = xb.x - l0b.x*s1 - l0b.y*s2;  s2 = s1; s1 = yo; o2.x = yo;
        yo = xb.y - l0b.z*s1 - l0b.w*s2;  s2 = s1; s1 = yo; o2.y = yo;
        yo = xb.z - l1b.x*s1 - l1b.y*s2;  s2 = s1; s1 = yo; o2.z = yo;
        yo = xb.w - l1b.z*s1 - l1b.w*s2;  s2 = s1; s1 = yo; o2.w = yo;

        float4* og = reinterpret_cast<float4*>(out + (size_t)br * TLEN);
        const int Gm = tr * 256 + g0;
        if (Gm < T4)     og[Gm]     = o1;
        if (Gm + 1 < T4) og[Gm + 1] = o2;

        // chain block state to next tile: fold through all 4 warp maps
        #pragma unroll
        for (int j = 0; j < 4; j++) {
            float n1 = wm[j][0]*bs0 + wm[j][1]*bs1 + wm[j][4];
            float n2 = wm[j][2]*bs0 + wm[j][3]*bs1 + wm[j][5];
            bs0 = n1; bs1 = n2;
        }

        alc = aln;
    }
}

extern "C" void kernel_launch(void* const* d_in, const int* in_sizes, int n_in,
                              void* d_out, int out_size)
{
    const float* y  = (const float*)d_in[0];
    const float* Ae = (const float*)d_in[1];
    const float* Al = (const float*)d_in[2];
    float* out = (float*)d_out;

    cudaFuncSetAttribute(diffks_fused,
                         cudaFuncAttributeMaxDynamicSharedMemorySize, SMEM_BYTES);

    diffks_fused<<<GRID, TPB, SMEM_BYTES>>>(y, Ae, Al, out);
}